// round 4
// baseline (speedup 1.0000x reference)
#include <cuda_runtime.h>
#include <math.h>

// Problem constants (fixed by setup_inputs)
#define BB 4
#define PP 900
#define DD 512
#define HH 8
#define DK 64
#define NBH 32          // B*H
#define SIDE 30
#define C1 32           // conv1 out channels

// ---------------- scratch (device globals) ----------------
__device__ float g_q[BB*PP*DD];                   // [3600][512]
__device__ float g_k[BB*PP*DD];                   // [3600][512]
__device__ float g_scores[(size_t)NBH*PP*PP];     // [32][900][900]  (becomes attn in place)
__device__ int   g_idx[NBH*PP];                   // [32][900] column argmax
__device__ float g_pmax[NBH*8*PP];                // partial col-max per row-chunk
__device__ int   g_pidx[NBH*8*PP];
__device__ float g_part[BB*PP*15];                // [4][900][15] partial dot-products

// ---------------- f32x2 helpers (exact: two independent fp32 ops) ----------------
typedef unsigned long long ull;

__device__ __forceinline__ ull packf2(float a, float b)
{
    ull r;
    asm("mov.b64 %0, {%1, %2};" : "=l"(r)
        : "r"(__float_as_uint(a)), "r"(__float_as_uint(b)));
    return r;
}
__device__ __forceinline__ void unpackf2(ull v, float& a, float& b)
{
    unsigned u0, u1;
    asm("mov.b64 {%0, %1}, %2;" : "=r"(u0), "=r"(u1) : "l"(v));
    a = __uint_as_float(u0);
    b = __uint_as_float(u1);
}
__device__ __forceinline__ ull fma2(ull a, ull b, ull c)
{
    ull d;
    asm("fma.rn.f32x2 %0, %1, %2, %3;" : "=l"(d) : "l"(a), "l"(b), "l"(c));
    return d;
}

// =====================================================================
// 1) Projection GEMM: C[m][n] = sum_k A[m][k] * W[n][k] + bias[n]
// =====================================================================
__global__ void proj_kernel(const float* __restrict__ A,
                            const float* __restrict__ W,
                            const float* __restrict__ bias,
                            int which)
{
    __shared__ float As[16][64];
    __shared__ float Bs[16][64];
    float* C = which ? g_k : g_q;

    int tid = threadIdx.x;
    int m0 = blockIdx.x * 64;
    int n0 = blockIdx.y * 64;
    int tx = tid & 15, ty = tid >> 4;

    float acc[4][4] = {};
    for (int k0 = 0; k0 < 512; k0 += 16) {
        #pragma unroll
        for (int i = 0; i < 4; i++) {
            int idx = tid + i * 256;
            int r = idx >> 4, kk = idx & 15;
            int m = m0 + r;
            As[kk][r] = (m < 3600) ? A[(size_t)m * 512 + k0 + kk] : 0.f;
            Bs[kk][r] = W[(size_t)(n0 + r) * 512 + k0 + kk];
        }
        __syncthreads();
        #pragma unroll
        for (int kk = 0; kk < 16; kk++) {
            float a[4], b[4];
            #pragma unroll
            for (int i = 0; i < 4; i++) a[i] = As[kk][ty * 4 + i];
            #pragma unroll
            for (int j = 0; j < 4; j++) b[j] = Bs[kk][tx * 4 + j];
            #pragma unroll
            for (int i = 0; i < 4; i++)
                #pragma unroll
                for (int j = 0; j < 4; j++)
                    acc[i][j] += a[i] * b[j];
        }
        __syncthreads();
    }
    #pragma unroll
    for (int i = 0; i < 4; i++) {
        int m = m0 + ty * 4 + i;
        if (m >= 3600) continue;
        #pragma unroll
        for (int j = 0; j < 4; j++) {
            int n = n0 + tx * 4 + j;
            C[(size_t)m * 512 + n] = acc[i][j] + bias[n];
        }
    }
}

// =====================================================================
// 2) scores[bh][p][w] = sum_c q[bh][p][c] * k[bh][w][c]   (K=64)
// =====================================================================
__global__ void scores_kernel()
{
    __shared__ float As[16][64];
    __shared__ float Bs[16][64];

    int z = blockIdx.z;
    int b = z >> 3, h = z & 7;
    const float* A  = g_q + (size_t)b * PP * DD + h * DK;
    const float* Bk = g_k + (size_t)b * PP * DD + h * DK;
    float* C = g_scores + (size_t)z * PP * PP;

    int tid = threadIdx.x;
    int m0 = blockIdx.x * 64;
    int n0 = blockIdx.y * 64;
    int tx = tid & 15, ty = tid >> 4;

    float acc[4][4] = {};
    for (int k0 = 0; k0 < 64; k0 += 16) {
        #pragma unroll
        for (int i = 0; i < 4; i++) {
            int idx = tid + i * 256;
            int r = idx >> 4, kk = idx & 15;
            As[kk][r] = (m0 + r < PP) ? A[(size_t)(m0 + r) * 512 + k0 + kk] : 0.f;
            Bs[kk][r] = (n0 + r < PP) ? Bk[(size_t)(n0 + r) * 512 + k0 + kk] : 0.f;
        }
        __syncthreads();
        #pragma unroll
        for (int kk = 0; kk < 16; kk++) {
            float a[4], b2[4];
            #pragma unroll
            for (int i = 0; i < 4; i++) a[i] = As[kk][ty * 4 + i];
            #pragma unroll
            for (int j = 0; j < 4; j++) b2[j] = Bs[kk][tx * 4 + j];
            #pragma unroll
            for (int i = 0; i < 4; i++)
                #pragma unroll
                for (int j = 0; j < 4; j++)
                    acc[i][j] += a[i] * b2[j];
        }
        __syncthreads();
    }
    #pragma unroll
    for (int i = 0; i < 4; i++) {
        int m = m0 + ty * 4 + i;
        if (m >= PP) continue;
        #pragma unroll
        for (int j = 0; j < 4; j++) {
            int n = n0 + tx * 4 + j;
            if (n < PP) C[(size_t)m * PP + n] = acc[i][j];
        }
    }
}

// =====================================================================
// 3) column argmax, two stages for parallelism
// =====================================================================
#define CHUNK 113   // 8 chunks: 7*113 + 109 = 900
__global__ void argmax_part_kernel()
{
    int bh = blockIdx.x;
    int ck = blockIdx.y;
    int r0 = ck * CHUNK;
    int len = min(CHUNK, PP - r0);
    const float* S0 = g_scores + (size_t)bh * PP * PP;
    for (int w = threadIdx.x; w < PP; w += 256) {
        const float* S = S0 + w;
        float best = -1e30f; int bi = 0;
        for (int r = 0; r < len; r++) {
            float v = S[(size_t)(r0 + r) * PP];
            if (v > best) { best = v; bi = r0 + r; }
        }
        g_pmax[(bh * 8 + ck) * PP + w] = best;
        g_pidx[(bh * 8 + ck) * PP + w] = bi;
    }
}

__global__ void argmax_reduce_kernel()
{
    int bh = blockIdx.x;
    int w = blockIdx.y * 256 + threadIdx.x;
    if (w >= PP) return;
    float best = -1e30f; int bi = 0;
    #pragma unroll
    for (int ck = 0; ck < 8; ck++) {
        float v = g_pmax[(bh * 8 + ck) * PP + w];
        if (v > best) { best = v; bi = g_pidx[(bh * 8 + ck) * PP + w]; }
    }
    g_idx[bh * PP + w] = bi;
}

// =====================================================================
// 4) gaussian modulation + /sqrt(dk) + row softmax, in place
// =====================================================================
__global__ void softmax_kernel()
{
    __shared__ float buf[PP];
    __shared__ float red[256];

    int row = blockIdx.x;
    int bh = row / PP, p0 = row % PP;
    int t = threadIdx.x;

    float ys0 = -1.f + (2.f / 29.f) * (float)(p0 / SIDE);
    float xs0 = -1.f + (2.f / 29.f) * (float)(p0 % SIDE);

    float* S = g_scores + (size_t)bh * PP * PP + (size_t)p0 * PP;
    const int* idx = g_idx + bh * PP;

    float lmax = -1e30f;
    for (int w = t; w < PP; w += 256) {
        int id = idx[w];
        float dy = ys0 - (float)(id / SIDE);
        float dx = xs0 - (float)(id % SIDE);
        float g = __expf(-(dx * dx + dy * dy) * (1.f / 50.f));
        float v = S[w] * g * 0.125f;
        buf[w] = v;
        lmax = fmaxf(lmax, v);
    }
    red[t] = lmax; __syncthreads();
    for (int s = 128; s > 0; s >>= 1) {
        if (t < s) red[t] = fmaxf(red[t], red[t + s]);
        __syncthreads();
    }
    float m = red[0];
    __syncthreads();

    float lsum = 0.f;
    for (int w = t; w < PP; w += 256) {
        float e = __expf(buf[w] - m);
        buf[w] = e;
        lsum += e;
    }
    red[t] = lsum; __syncthreads();
    for (int s = 128; s > 0; s >>= 1) {
        if (t < s) red[t] += red[t + s];
        __syncthreads();
    }
    float inv = 1.f / red[0];
    for (int w = t; w < PP; w += 256) S[w] = buf[w] * inv;
}

// =====================================================================
// 5) FUSED conv1 (8->32, relu) + conv2 (32->8, relu) + value-dot,
//    pure fp32 via packed fma.rn.f32x2 (bit-exact vs scalar fp32).
//
// Tile: output 60 x 16, grid (15, 57, 4), 256 threads.
// smem:
//   Xs  [8 ic][20 rows][72 cols] fp32  (attn tile + halo, zero-padded)
//   C1s [32 oc][stride 1153]: [18 rows][64 cols] fp32 (+1 pad float)
//   Ws1 [(ic*9+tap)][32 oc] fp32
//   Wd2 [(ic*9+tap)*8+oc] float2 duplicated (ull)
//   sb2 [8]
// =====================================================================
#define XS_OFF   0
#define XS_SZ    (8*20*72*4)            // 46080
#define C1_OFF   XS_SZ                  // 46080
#define C1_STRIDE 1153
#define C1_SZ    (32*C1_STRIDE*4)       // 147584
#define WS1_OFF  (C1_OFF + C1_SZ)       // 193664
#define WS1_SZ   (2304*4)
#define WD2_OFF  (WS1_OFF + WS1_SZ)     // 202880
#define WD2_SZ   (2304*8)
#define SB2_OFF  (WD2_OFF + WD2_SZ)     // 221312
#define FUSED_SMEM (SB2_OFF + 32)       // 221344

__global__ __launch_bounds__(256)
void fused_conv_kernel(const float* __restrict__ w1, const float* __restrict__ b1,
                       const float* __restrict__ w2, const float* __restrict__ b2,
                       const float* __restrict__ value)
{
    extern __shared__ char smem[];
    float* Xs  = (float*)(smem + XS_OFF);
    float* C1s = (float*)(smem + C1_OFF);
    float* Ws1 = (float*)(smem + WS1_OFF);
    ull*   Wd2 = (ull*)(smem + WD2_OFF);
    float* sb2 = (float*)(smem + SB2_OFF);

    int n   = blockIdx.z;
    int ty0 = blockIdx.y * 16;
    int tx0 = blockIdx.x * 60;
    int tid = threadIdx.x;
    int warp = tid >> 5;
    int lane = tid & 31;

    // ---- weight smem fill ----
    for (int e = tid; e < 2304; e += 256) {
        int oc = e & 31;
        int ictap = e >> 5;                 // ic*9+tap
        int ic = ictap / 9, tap = ictap % 9;
        Ws1[e] = w1[oc * 72 + ic * 9 + tap];
    }
    for (int e = tid; e < 2304; e += 256) {
        int oc = e & 7;
        int ictap = e >> 3;
        int ic = ictap / 9, tap = ictap % 9;
        float w = w2[oc * 288 + ic * 9 + tap];
        Wd2[e] = packf2(w, w);
    }
    if (tid < 8) sb2[tid] = b2[tid];

    // ---- input tile: Xs[ic][row][cx], cx0 <-> gx = tx0-4 (cols 2..67 valid) ----
    for (int e = tid; e < 8 * 20 * 72; e += 256) {
        int ic  = e / (20 * 72);
        int rem = e % (20 * 72);
        int row = rem / 72, cx = rem % 72;
        int gy = ty0 - 2 + row;
        int gx = tx0 - 4 + cx;
        float v = 0.f;
        if (cx >= 2 && cx < 68 && (unsigned)gy < PP && (unsigned)gx < PP)
            v = g_scores[(((size_t)(n * 8 + ic)) * PP + gy) * PP + gx];
        Xs[e] = v;
    }
    __syncthreads();

    // ================= conv1: weight-stationary, lane = oc =================
    // C1 region: rows 0..17 (gy = ty0-1+r), cols 0..63 (gx = tx0-1+c)
    // 48 warp-blocks: rb in 0..5 (3 rows), cb in 0..7 (8 cols / 4 pairs)
    {
        float biasv = b1[lane];
        for (int blk = warp; blk < 48; blk += 8) {
            int rb = blk >> 3, cb = blk & 7;
            int r0 = rb * 3;
            int cx0 = cb * 8;

            ull acc[3][4];
            ull bp = packf2(biasv, biasv);
            #pragma unroll
            for (int rl = 0; rl < 3; rl++)
                #pragma unroll
                for (int p = 0; p < 4; p++) acc[rl][p] = bp;

            for (int ic = 0; ic < 8; ic++) {
                // 9 weight pairs for (oc=lane, ic)
                ull wp[9];
                #pragma unroll
                for (int tap = 0; tap < 9; tap++) {
                    float w = Ws1[(ic * 9 + tap) * 32 + lane];
                    wp[tap] = packf2(w, w);
                }
                const float* xb = Xs + (ic * 20) * 72;
                #pragma unroll
                for (int xr = 0; xr < 5; xr++) {
                    const float4* rp = (const float4*)(xb + (r0 + xr) * 72 + cx0);
                    float4 fa = rp[0], fb = rp[1], fc = rp[2];
                    float xs_[12] = { fa.x, fa.y, fa.z, fa.w,
                                      fb.x, fb.y, fb.z, fb.w,
                                      fc.x, fc.y, fc.z, fc.w };
                    ull pr[9];
                    #pragma unroll
                    for (int j = 0; j < 9; j++)
                        pr[j] = packf2(xs_[j + 2], xs_[j + 3]);
                    #pragma unroll
                    for (int ky = 0; ky < 3; ky++) {
                        int rl = xr - ky;
                        if (rl < 0 || rl > 2) continue;
                        #pragma unroll
                        for (int kx = 0; kx < 3; kx++) {
                            ull w = wp[ky * 3 + kx];
                            #pragma unroll
                            for (int p = 0; p < 4; p++)
                                acc[rl][p] = fma2(w, pr[2 * p + kx], acc[rl][p]);
                        }
                    }
                }
            }
            // relu + boundary-zero + store (lane = channel, conflict-free via stride 1153)
            #pragma unroll
            for (int rl = 0; rl < 3; rl++) {
                int r = r0 + rl;
                int gy = ty0 - 1 + r;
                bool rok = ((unsigned)gy < PP);
                #pragma unroll
                for (int p = 0; p < 4; p++) {
                    float v0, v1;
                    unpackf2(acc[rl][p], v0, v1);
                    int c = cb * 8 + 2 * p;
                    int gx0 = tx0 - 1 + c;
                    float o0 = (rok && (unsigned)gx0 < PP) ? fmaxf(v0, 0.f) : 0.f;
                    float o1 = (rok && (unsigned)(gx0 + 1) < PP) ? fmaxf(v1, 0.f) : 0.f;
                    float* dst = C1s + lane * C1_STRIDE + r * 64 + c;
                    dst[0] = o0;
                    dst[1] = o1;
                }
            }
        }
    }
    __syncthreads();

    // ================= conv2 + value-dot: thread = (y, 4-px strip) =================
    {
        int y  = tid >> 4;          // 0..15
        int st = tid & 15;          // 0..15
        int c0 = st * 4;            // output cols c0..c0+3 (valid < 60)

        ull acc[8][2];
        #pragma unroll
        for (int oc = 0; oc < 8; oc++) {
            ull bp = packf2(sb2[oc], sb2[oc]);
            acc[oc][0] = bp; acc[oc][1] = bp;
        }

        for (int ic = 0; ic < 32; ic++) {
            const float* cb = C1s + ic * C1_STRIDE;
            float xv[3][6];
            #pragma unroll
            for (int dr = 0; dr < 3; dr++)
                #pragma unroll
                for (int dc = 0; dc < 6; dc++) {
                    int c = c0 + dc; if (c > 63) c = 63;   // clamped reads feed discarded cols only
                    xv[dr][dc] = cb[(y + dr) * 64 + c];
                }
            ull pro[3][5];
            #pragma unroll
            for (int dr = 0; dr < 3; dr++)
                #pragma unroll
                for (int o = 0; o < 5; o++)
                    pro[dr][o] = packf2(xv[dr][o], xv[dr][o + 1]);

            const ull* wb = Wd2 + (ic * 9) * 8;
            #pragma unroll
            for (int ky = 0; ky < 3; ky++)
                #pragma unroll
                for (int kx = 0; kx < 3; kx++) {
                    const ull* wt = wb + (ky * 3 + kx) * 8;
                    ull x0 = pro[ky][kx];
                    ull x1 = pro[ky][kx + 2];
                    #pragma unroll
                    for (int oc = 0; oc < 8; oc++) {
                        ull w = wt[oc];
                        acc[oc][0] = fma2(w, x0, acc[oc][0]);
                        acc[oc][1] = fma2(w, x1, acc[oc][1]);
                    }
                }
        }

        // relu + dot(value) over this thread's 4 cols, summed over 8 oc
        float vals[4];
        #pragma unroll
        for (int j = 0; j < 4; j++) {
            int x = c0 + j;
            vals[j] = (x < 60) ? value[n * PP + tx0 + x] : 0.f;
        }
        float s = 0.f;
        #pragma unroll
        for (int oc = 0; oc < 8; oc++) {
            float a0, a1, a2, a3;
            unpackf2(acc[oc][0], a0, a1);
            unpackf2(acc[oc][1], a2, a3);
            s += vals[0] * fmaxf(a0, 0.f) + vals[1] * fmaxf(a1, 0.f)
               + vals[2] * fmaxf(a2, 0.f) + vals[3] * fmaxf(a3, 0.f);
        }
        // reduce over the 16 strip-lanes of this output row
        #pragma unroll
        for (int off = 8; off > 0; off >>= 1)
            s += __shfl_down_sync(0xffffffffu, s, off, 16);
        int gy = ty0 + y;
        if ((lane & 15) == 0 && gy < PP)
            g_part[(n * PP + gy) * 15 + blockIdx.x] = s;
    }
}

// =====================================================================
// 6) finalize: out[b][p] = (1/8) * sum_tiles partials
// =====================================================================
__global__ void finalize_kernel(float* __restrict__ out)
{
    int i = blockIdx.x * 256 + threadIdx.x;
    if (i >= BB * PP) return;
    float s = 0.f;
    #pragma unroll
    for (int t = 0; t < 15; t++) s += g_part[i * 15 + t];
    out[i] = s * 0.125f;
}

// =====================================================================
extern "C" void kernel_launch(void* const* d_in, const int* in_sizes, int n_in,
                              void* d_out, int out_size)
{
    const float* query = (const float*)d_in[0];
    const float* key_t = (const float*)d_in[1];
    const float* value = (const float*)d_in[2];
    const float* Wq    = (const float*)d_in[3];
    const float* bq    = (const float*)d_in[4];
    const float* Wk    = (const float*)d_in[5];
    const float* bk    = (const float*)d_in[6];
    const float* w1    = (const float*)d_in[7];
    const float* b1    = (const float*)d_in[8];
    const float* w2    = (const float*)d_in[9];
    const float* b2    = (const float*)d_in[10];

    static int smem_set = 0;
    if (!smem_set) {
        cudaFuncSetAttribute(fused_conv_kernel,
                             cudaFuncAttributeMaxDynamicSharedMemorySize, FUSED_SMEM);
        smem_set = 1;
    }

    dim3 gp(57, 8);
    proj_kernel<<<gp, 256>>>(query, Wq, bq, 0);
    proj_kernel<<<gp, 256>>>(key_t, Wk, bk, 1);

    dim3 gs(15, 15, NBH);
    scores_kernel<<<gs, 256>>>();

    dim3 ga(NBH, 8);
    argmax_part_kernel<<<ga, 256>>>();
    dim3 gr(NBH, 4);
    argmax_reduce_kernel<<<gr, 256>>>();

    softmax_kernel<<<NBH * PP, 256>>>();

    dim3 gc(15, 57, BB);
    fused_conv_kernel<<<gc, 256, FUSED_SMEM>>>(w1, b1, w2, b2, value);

    finalize_kernel<<<15, 256>>>((float*)d_out);
}

// round 9
// speedup vs baseline: 1.2166x; 1.2166x over previous
#include <cuda_runtime.h>
#include <cuda_fp16.h>
#include <math.h>

// Problem constants (fixed by setup_inputs)
#define BB 4
#define PP 900
#define DD 512
#define HH 8
#define DK 64
#define NBH 32          // B*H
#define SIDE 30
#define C1 32           // conv1 out channels

// ---------------- scratch (device globals) ----------------
__device__ float g_q[BB*PP*DD];                   // [3600][512]
__device__ float g_k[BB*PP*DD];                   // [3600][512]
__device__ float g_scores[(size_t)NBH*PP*PP];     // [32][900][900]  (becomes attn in place)
__device__ int   g_idx[NBH*PP];                   // [32][900] column argmax
__device__ float g_pmax[NBH*8*PP];                // partial col-max per row-chunk
__device__ int   g_pidx[NBH*8*PP];
__device__ float g_conv1[(size_t)BB*C1*PP*PP];    // [4][32][900][900]
__device__ float g_part[BB*PP*15];                // [4][900][15] partial dot-products

// =====================================================================
// 1) Projection GEMM: C[m][n] = sum_k A[m][k] * W[n][k] + bias[n]
// =====================================================================
__global__ void proj_kernel(const float* __restrict__ A,
                            const float* __restrict__ W,
                            const float* __restrict__ bias,
                            int which)
{
    __shared__ float As[16][64];
    __shared__ float Bs[16][64];
    float* C = which ? g_k : g_q;

    int tid = threadIdx.x;
    int m0 = blockIdx.x * 64;
    int n0 = blockIdx.y * 64;
    int tx = tid & 15, ty = tid >> 4;

    float acc[4][4] = {};
    for (int k0 = 0; k0 < 512; k0 += 16) {
        #pragma unroll
        for (int i = 0; i < 4; i++) {
            int idx = tid + i * 256;
            int r = idx >> 4, kk = idx & 15;
            int m = m0 + r;
            As[kk][r] = (m < 3600) ? A[(size_t)m * 512 + k0 + kk] : 0.f;
            Bs[kk][r] = W[(size_t)(n0 + r) * 512 + k0 + kk];
        }
        __syncthreads();
        #pragma unroll
        for (int kk = 0; kk < 16; kk++) {
            float a[4], b[4];
            #pragma unroll
            for (int i = 0; i < 4; i++) a[i] = As[kk][ty * 4 + i];
            #pragma unroll
            for (int j = 0; j < 4; j++) b[j] = Bs[kk][tx * 4 + j];
            #pragma unroll
            for (int i = 0; i < 4; i++)
                #pragma unroll
                for (int j = 0; j < 4; j++)
                    acc[i][j] += a[i] * b[j];
        }
        __syncthreads();
    }
    #pragma unroll
    for (int i = 0; i < 4; i++) {
        int m = m0 + ty * 4 + i;
        if (m >= 3600) continue;
        #pragma unroll
        for (int j = 0; j < 4; j++) {
            int n = n0 + tx * 4 + j;
            C[(size_t)m * 512 + n] = acc[i][j] + bias[n];
        }
    }
}

// =====================================================================
// 2) scores[bh][p][w] = sum_c q[bh][p][c] * k[bh][w][c]   (K=64)
// =====================================================================
__global__ void scores_kernel()
{
    __shared__ float As[16][64];
    __shared__ float Bs[16][64];

    int z = blockIdx.z;
    int b = z >> 3, h = z & 7;
    const float* A  = g_q + (size_t)b * PP * DD + h * DK;
    const float* Bk = g_k + (size_t)b * PP * DD + h * DK;
    float* C = g_scores + (size_t)z * PP * PP;

    int tid = threadIdx.x;
    int m0 = blockIdx.x * 64;
    int n0 = blockIdx.y * 64;
    int tx = tid & 15, ty = tid >> 4;

    float acc[4][4] = {};
    for (int k0 = 0; k0 < 64; k0 += 16) {
        #pragma unroll
        for (int i = 0; i < 4; i++) {
            int idx = tid + i * 256;
            int r = idx >> 4, kk = idx & 15;
            As[kk][r] = (m0 + r < PP) ? A[(size_t)(m0 + r) * 512 + k0 + kk] : 0.f;
            Bs[kk][r] = (n0 + r < PP) ? Bk[(size_t)(n0 + r) * 512 + k0 + kk] : 0.f;
        }
        __syncthreads();
        #pragma unroll
        for (int kk = 0; kk < 16; kk++) {
            float a[4], b2[4];
            #pragma unroll
            for (int i = 0; i < 4; i++) a[i] = As[kk][ty * 4 + i];
            #pragma unroll
            for (int j = 0; j < 4; j++) b2[j] = Bs[kk][tx * 4 + j];
            #pragma unroll
            for (int i = 0; i < 4; i++)
                #pragma unroll
                for (int j = 0; j < 4; j++)
                    acc[i][j] += a[i] * b2[j];
        }
        __syncthreads();
    }
    #pragma unroll
    for (int i = 0; i < 4; i++) {
        int m = m0 + ty * 4 + i;
        if (m >= PP) continue;
        #pragma unroll
        for (int j = 0; j < 4; j++) {
            int n = n0 + tx * 4 + j;
            if (n < PP) C[(size_t)m * PP + n] = acc[i][j];
        }
    }
}

// =====================================================================
// 3) column argmax, two stages (validated in R4)
// =====================================================================
#define CHUNK 113   // 8 chunks: 7*113 + 109 = 900
__global__ void argmax_part_kernel()
{
    int bh = blockIdx.x;
    int ck = blockIdx.y;
    int r0 = ck * CHUNK;
    int len = min(CHUNK, PP - r0);
    const float* S0 = g_scores + (size_t)bh * PP * PP;
    for (int w = threadIdx.x; w < PP; w += 256) {
        const float* S = S0 + w;
        float best = -1e30f; int bi = 0;
        for (int r = 0; r < len; r++) {
            float v = S[(size_t)(r0 + r) * PP];
            if (v > best) { best = v; bi = r0 + r; }
        }
        g_pmax[(bh * 8 + ck) * PP + w] = best;
        g_pidx[(bh * 8 + ck) * PP + w] = bi;
    }
}

__global__ void argmax_reduce_kernel()
{
    int bh = blockIdx.x;
    int w = blockIdx.y * 256 + threadIdx.x;
    if (w >= PP) return;
    float best = -1e30f; int bi = 0;
    #pragma unroll
    for (int ck = 0; ck < 8; ck++) {
        float v = g_pmax[(bh * 8 + ck) * PP + w];
        if (v > best) { best = v; bi = g_pidx[(bh * 8 + ck) * PP + w]; }
    }
    g_idx[bh * PP + w] = bi;
}

// =====================================================================
// 4) gaussian modulation + /sqrt(dk) + row softmax, in place
// =====================================================================
__global__ void softmax_kernel()
{
    __shared__ float buf[PP];
    __shared__ float red[256];

    int row = blockIdx.x;
    int bh = row / PP, p0 = row % PP;
    int t = threadIdx.x;

    float ys0 = -1.f + (2.f / 29.f) * (float)(p0 / SIDE);
    float xs0 = -1.f + (2.f / 29.f) * (float)(p0 % SIDE);

    float* S = g_scores + (size_t)bh * PP * PP + (size_t)p0 * PP;
    const int* idx = g_idx + bh * PP;

    float lmax = -1e30f;
    for (int w = t; w < PP; w += 256) {
        int id = idx[w];
        float dy = ys0 - (float)(id / SIDE);
        float dx = xs0 - (float)(id % SIDE);
        float g = __expf(-(dx * dx + dy * dy) * (1.f / 50.f));
        float v = S[w] * g * 0.125f;
        buf[w] = v;
        lmax = fmaxf(lmax, v);
    }
    red[t] = lmax; __syncthreads();
    for (int s = 128; s > 0; s >>= 1) {
        if (t < s) red[t] = fmaxf(red[t], red[t + s]);
        __syncthreads();
    }
    float m = red[0];
    __syncthreads();

    float lsum = 0.f;
    for (int w = t; w < PP; w += 256) {
        float e = __expf(buf[w] - m);
        buf[w] = e;
        lsum += e;
    }
    red[t] = lsum; __syncthreads();
    for (int s = 128; s > 0; s >>= 1) {
        if (t < s) red[t] += red[t + s];
        __syncthreads();
    }
    float inv = 1.f / red[0];
    for (int w = t; w < PP; w += 256) S[w] = buf[w] * inv;
}

// =====================================================================
// 5a) conv1 via tensor cores (m16n8k8 f16, f32 acc) with SCALED hi/lo
//     fp16 splitting; fp32 output to g_conv1 (gmem).
//     Output tile per CTA: 64 cols x 16 rows. Grid (15, 57, 4).
// =====================================================================
#define LO_SCALE 2048.0f
#define LO_INV   (1.0f / 2048.0f)
#define X1_W     66    // input cols: gx = tx0-1+j, j=0..65

__device__ __forceinline__ void hmma_16x8x8(float& c0, float& c1, float& c2, float& c3,
                                            unsigned a0, unsigned a1, unsigned b0)
{
    asm volatile(
        "mma.sync.aligned.m16n8k8.row.col.f32.f16.f16.f32 "
        "{%0,%1,%2,%3}, {%4,%5}, {%6}, {%0,%1,%2,%3};\n"
        : "+f"(c0), "+f"(c1), "+f"(c2), "+f"(c3)
        : "r"(a0), "r"(a1), "r"(b0));
}

__device__ __forceinline__ unsigned pack_hh(__half a, __half b)
{
    __half2 h = __halves2half2(a, b);
    return *reinterpret_cast<unsigned*>(&h);
}

// hi = fp16(x); lo = fp16((x - hi) * 2048)
__device__ __forceinline__ void split2s(float a, float b, unsigned& hi, unsigned& lo)
{
    __half ha = __float2half_rn(a), hb = __float2half_rn(b);
    hi = pack_hh(ha, hb);
    lo = pack_hh(__float2half_rn((a - __half2float(ha)) * LO_SCALE),
                 __float2half_rn((b - __half2float(hb)) * LO_SCALE));
}

__global__ __launch_bounds__(256)
void conv1_mma_kernel(const float* __restrict__ w1, const float* __restrict__ b1)
{
    // 18 rows x 66 cols x 8ch fp16 records, hi + lo
    __shared__ char XpH[18 * X1_W * 16];
    __shared__ char XpL[18 * X1_W * 16];
    __shared__ unsigned W1H[9 * 4 * 32];
    __shared__ unsigned W1L[9 * 4 * 32];
    __shared__ float sb1[32];

    int n   = blockIdx.z;
    int ty0 = blockIdx.y * 16;
    int tx0 = blockIdx.x * 64;
    int tid = threadIdx.x;
    int wid = tid >> 5;
    int lane = tid & 31;
    int t = lane & 3;        // channel-pair selector (k)
    int g = lane >> 2;       // pixel-in-fragment (m) / oc (n)

    // ---- weight fragments, scaled hi/lo: B[k=ic][n=oc] = w1[oc][ic][tap] ----
    for (int i = tid; i < 9 * 4 * 32; i += 256) {
        int tap = i >> 7;
        int nt  = (i >> 5) & 3;
        int ln  = i & 31;
        int lt = ln & 3, lg = ln >> 2;
        int oc1 = nt * 8 + lg;
        split2s(w1[oc1 * 72 + (2 * lt) * 9 + tap],
                w1[oc1 * 72 + (2 * lt + 1) * 9 + tap], W1H[i], W1L[i]);
    }
    if (tid < 32) sb1[tid] = b1[tid];

    // ---- input tile: rows gy=ty0-1+i (i 0..17), cols gx=tx0-1+j (j 0..65) ----
    for (int e = tid; e < 18 * X1_W; e += 256) {
        int rI = e / X1_W, j = e % X1_W;
        int gy = ty0 - 1 + rI, gx = tx0 - 1 + j;
        bool inb = ((unsigned)gy < (unsigned)PP) && ((unsigned)gx < (unsigned)PP);
        unsigned rh[4], rl[4];
        #pragma unroll
        for (int icp = 0; icp < 4; icp++) {
            float f0 = 0.f, f1 = 0.f;
            if (inb) {
                const float* base = g_scores + (((size_t)(n * 8 + 2 * icp)) * PP + gy) * PP + gx;
                f0 = base[0];
                f1 = base[(size_t)PP * PP];
            }
            split2s(f0, f1, rh[icp], rl[icp]);
        }
        *(uint4*)(XpH + e * 16) = make_uint4(rh[0], rh[1], rh[2], rh[3]);
        *(uint4*)(XpL + e * 16) = make_uint4(rl[0], rl[1], rl[2], rl[3]);
    }
    __syncthreads();

    // ---- fragments resident per lane ----
    unsigned w1fh[9][4], w1fl[9][4];
    #pragma unroll
    for (int tap = 0; tap < 9; tap++)
        #pragma unroll
        for (int nt = 0; nt < 4; nt++) {
            w1fh[tap][nt] = W1H[(tap * 4 + nt) * 32 + lane];
            w1fl[tap][nt] = W1L[(tap * 4 + nt) * 32 + lane];
        }

    // ---- 64 units: y (0..15) x strip s (0..3), 8 per warp ----
    for (int it = wid; it < 64; it += 8) {
        int y = it >> 2, s = it & 3;
        float ah[4][4] = {};
        float al[4][4] = {};
        #pragma unroll
        for (int tap = 0; tap < 9; tap++) {
            int ky = tap / 3, kx = tap % 3;
            // output pixel x = s*16+g needs input col j = x+kx (gx = tx0+x-1+kx)
            int j0 = s * 16 + kx + g;
            int boff = ((y + ky) * X1_W + j0) * 16 + t * 4;
            unsigned a0h = *(const unsigned*)(XpH + boff);
            unsigned a1h = *(const unsigned*)(XpH + boff + 8 * 16);
            unsigned a0l = *(const unsigned*)(XpL + boff);
            unsigned a1l = *(const unsigned*)(XpL + boff + 8 * 16);
            #pragma unroll
            for (int nt = 0; nt < 4; nt++) {
                hmma_16x8x8(ah[nt][0], ah[nt][1], ah[nt][2], ah[nt][3], a0h, a1h, w1fh[tap][nt]);
                hmma_16x8x8(al[nt][0], al[nt][1], al[nt][2], al[nt][3], a0l, a1l, w1fh[tap][nt]);
                hmma_16x8x8(al[nt][0], al[nt][1], al[nt][2], al[nt][3], a0h, a1h, w1fl[tap][nt]);
            }
        }
        // combine + bias + relu + fp32 store to gmem
        int gy = ty0 + y;
        if (gy < PP) {
            int gx0 = tx0 + s * 16 + g;       // pixel for c0,c1
            int gx8 = gx0 + 8;                // pixel for c2,c3
            #pragma unroll
            for (int nt = 0; nt < 4; nt++) {
                int ocA = nt * 8 + 2 * t;
                float bA = sb1[ocA], bB = sb1[ocA + 1];
                float y0 = fmaxf(ah[nt][0] + al[nt][0] * LO_INV + bA, 0.f);
                float y1 = fmaxf(ah[nt][1] + al[nt][1] * LO_INV + bB, 0.f);
                float y2 = fmaxf(ah[nt][2] + al[nt][2] * LO_INV + bA, 0.f);
                float y3 = fmaxf(ah[nt][3] + al[nt][3] * LO_INV + bB, 0.f);
                size_t rowA = ((size_t)(n * C1 + ocA) * PP + gy) * PP;
                size_t rowB = ((size_t)(n * C1 + ocA + 1) * PP + gy) * PP;
                if (gx0 < PP) {
                    g_conv1[rowA + gx0] = y0;
                    g_conv1[rowB + gx0] = y1;
                }
                if (gx8 < PP) {
                    g_conv1[rowA + gx8] = y2;
                    g_conv1[rowB + gx8] = y3;
                }
            }
        }
    }
}

// =====================================================================
// 5b) conv2: 32 -> 8 channels, 3x3 SAME, relu, fused with value-dot
//     (byte-for-byte the R1 kernel that passed at 1.1e-7)
// =====================================================================
__global__ void conv2_kernel(const float* __restrict__ w2, const float* __restrict__ b2,
                             const float* __restrict__ value)
{
    __shared__ float sin_[8][18][66];
    __shared__ float sw[2304];   // [(ic*9+tap)*8 + oc]
    __shared__ float sb[8];

    int n = blockIdx.z;
    int ty0 = blockIdx.y * 16;
    int tx0 = blockIdx.x * 64;
    int tid = threadIdx.x;

    for (int i = tid; i < 2304; i += 256) {
        int ict = i >> 3, oc = i & 7;
        sw[i] = w2[oc * 288 + ict];
    }
    if (tid < 8) sb[tid] = b2[tid];

    int tx = tid & 15, ty = tid >> 4;
    int ox = tx * 4, oy = ty;
    int gy = ty0 + oy;

    float acc[8][4];
    #pragma unroll
    for (int o = 0; o < 8; o++) {
        acc[o][0] = 0.f; acc[o][1] = 0.f; acc[o][2] = 0.f; acc[o][3] = 0.f;
    }

    for (int chunk = 0; chunk < 4; chunk++) {
        __syncthreads();
        for (int i = tid; i < 8 * 18 * 66; i += 256) {
            int ic = i / (18 * 66);
            int rem = i % (18 * 66);
            int r = rem / 66, c = rem % 66;
            int gy2 = ty0 - 1 + r, gx2 = tx0 - 1 + c;
            float v = 0.f;
            if ((unsigned)gy2 < PP && (unsigned)gx2 < PP)
                v = g_conv1[((size_t)(n * C1 + chunk * 8 + ic) * PP + gy2) * PP + gx2];
            sin_[ic][r][c] = v;
        }
        __syncthreads();

        for (int ic = 0; ic < 8; ic++) {
            float pt[3][6];
            #pragma unroll
            for (int r = 0; r < 3; r++)
                #pragma unroll
                for (int c = 0; c < 6; c++)
                    pt[r][c] = sin_[ic][oy + r][ox + c];
            int icg = chunk * 8 + ic;
            #pragma unroll
            for (int ky = 0; ky < 3; ky++)
                #pragma unroll
                for (int kx = 0; kx < 3; kx++) {
                    int wb = (icg * 9 + ky * 3 + kx) * 8;
                    #pragma unroll
                    for (int o = 0; o < 8; o++) {
                        float w = sw[wb + o];
                        #pragma unroll
                        for (int j = 0; j < 4; j++)
                            acc[o][j] += w * pt[ky][kx + j];
                    }
                }
        }
    }

    // bias + relu + dot with value + sum over the 8 output channels
    float s = 0.f;
    #pragma unroll
    for (int j = 0; j < 4; j++) {
        int gx = tx0 + ox + j;
        float v = (gx < PP) ? value[n * PP + gx] : 0.f;
        float col = 0.f;
        #pragma unroll
        for (int o = 0; o < 8; o++)
            col += fmaxf(acc[o][j] + sb[o], 0.f);
        s += col * v;
    }
    if (gy >= PP) s = 0.f;

    // reduce across the 16 tx lanes of this output row
    #pragma unroll
    for (int off = 8; off > 0; off >>= 1)
        s += __shfl_down_sync(0xffffffffu, s, off, 16);

    if (tx == 0 && gy < PP)
        g_part[(n * PP + gy) * 15 + blockIdx.x] = s;
}

// =====================================================================
// 6) finalize: out[b][p] = (1/8) * sum_tiles partials
// =====================================================================
__global__ void finalize_kernel(float* __restrict__ out)
{
    int i = blockIdx.x * 256 + threadIdx.x;
    if (i >= BB * PP) return;
    float s = 0.f;
    #pragma unroll
    for (int t = 0; t < 15; t++) s += g_part[i * 15 + t];
    out[i] = s * 0.125f;
}

// =====================================================================
extern "C" void kernel_launch(void* const* d_in, const int* in_sizes, int n_in,
                              void* d_out, int out_size)
{
    const float* query = (const float*)d_in[0];
    const float* key_t = (const float*)d_in[1];
    const float* value = (const float*)d_in[2];
    const float* Wq    = (const float*)d_in[3];
    const float* bq    = (const float*)d_in[4];
    const float* Wk    = (const float*)d_in[5];
    const float* bk    = (const float*)d_in[6];
    const float* w1    = (const float*)d_in[7];
    const float* b1    = (const float*)d_in[8];
    const float* w2    = (const float*)d_in[9];
    const float* b2    = (const float*)d_in[10];

    dim3 gp(57, 8);
    proj_kernel<<<gp, 256>>>(query, Wq, bq, 0);
    proj_kernel<<<gp, 256>>>(key_t, Wk, bk, 1);

    dim3 gs(15, 15, NBH);
    scores_kernel<<<gs, 256>>>();

    dim3 ga(NBH, 8);
    argmax_part_kernel<<<ga, 256>>>();
    dim3 gr(NBH, 4);
    argmax_reduce_kernel<<<gr, 256>>>();

    softmax_kernel<<<NBH * PP, 256>>>();

    dim3 gc(15, 57, BB);
    conv1_mma_kernel<<<gc, 256>>>(w1, b1);
    conv2_kernel<<<gc, 256>>>(w2, b2, value);

    finalize_kernel<<<15, 256>>>((float*)d_out);
}

// round 10
// speedup vs baseline: 1.4533x; 1.1946x over previous
#include <cuda_runtime.h>
#include <cuda_fp16.h>
#include <math.h>

// Problem constants (fixed by setup_inputs)
#define BB 4
#define PP 900
#define DD 512
#define HH 8
#define DK 64
#define NBH 32          // B*H
#define SIDE 30
#define C1 32           // conv1 out channels

// ---------------- scratch (device globals) ----------------
__device__ float g_q[BB*PP*DD];                   // [3600][512]
__device__ float g_k[BB*PP*DD];                   // [3600][512]
__device__ float g_scores[(size_t)NBH*PP*PP];     // [32][900][900]  (becomes attn in place)
__device__ int   g_idx[NBH*PP];                   // [32][900] column argmax
__device__ float g_pmax[NBH*8*PP];                // partial col-max per row-chunk
__device__ int   g_pidx[NBH*8*PP];
__device__ float g_conv1[(size_t)BB*C1*PP*PP];    // [4][32][900][900]
__device__ float g_part[BB*PP*15];                // [4][900][15] partial dot-products

// =====================================================================
// 1) Projection GEMM: C[m][n] = sum_k A[m][k] * W[n][k] + bias[n]
// =====================================================================
__global__ void proj_kernel(const float* __restrict__ A,
                            const float* __restrict__ W,
                            const float* __restrict__ bias,
                            int which)
{
    __shared__ float As[16][64];
    __shared__ float Bs[16][64];
    float* C = which ? g_k : g_q;

    int tid = threadIdx.x;
    int m0 = blockIdx.x * 64;
    int n0 = blockIdx.y * 64;
    int tx = tid & 15, ty = tid >> 4;

    float acc[4][4] = {};
    for (int k0 = 0; k0 < 512; k0 += 16) {
        #pragma unroll
        for (int i = 0; i < 4; i++) {
            int idx = tid + i * 256;
            int r = idx >> 4, kk = idx & 15;
            int m = m0 + r;
            As[kk][r] = (m < 3600) ? A[(size_t)m * 512 + k0 + kk] : 0.f;
            Bs[kk][r] = W[(size_t)(n0 + r) * 512 + k0 + kk];
        }
        __syncthreads();
        #pragma unroll
        for (int kk = 0; kk < 16; kk++) {
            float a[4], b[4];
            #pragma unroll
            for (int i = 0; i < 4; i++) a[i] = As[kk][ty * 4 + i];
            #pragma unroll
            for (int j = 0; j < 4; j++) b[j] = Bs[kk][tx * 4 + j];
            #pragma unroll
            for (int i = 0; i < 4; i++)
                #pragma unroll
                for (int j = 0; j < 4; j++)
                    acc[i][j] += a[i] * b[j];
        }
        __syncthreads();
    }
    #pragma unroll
    for (int i = 0; i < 4; i++) {
        int m = m0 + ty * 4 + i;
        if (m >= 3600) continue;
        #pragma unroll
        for (int j = 0; j < 4; j++) {
            int n = n0 + tx * 4 + j;
            C[(size_t)m * 512 + n] = acc[i][j] + bias[n];
        }
    }
}

// =====================================================================
// 2) scores[bh][p][w] = sum_c q[bh][p][c] * k[bh][w][c]   (K=64)
// =====================================================================
__global__ void scores_kernel()
{
    __shared__ float As[16][64];
    __shared__ float Bs[16][64];

    int z = blockIdx.z;
    int b = z >> 3, h = z & 7;
    const float* A  = g_q + (size_t)b * PP * DD + h * DK;
    const float* Bk = g_k + (size_t)b * PP * DD + h * DK;
    float* C = g_scores + (size_t)z * PP * PP;

    int tid = threadIdx.x;
    int m0 = blockIdx.x * 64;
    int n0 = blockIdx.y * 64;
    int tx = tid & 15, ty = tid >> 4;

    float acc[4][4] = {};
    for (int k0 = 0; k0 < 64; k0 += 16) {
        #pragma unroll
        for (int i = 0; i < 4; i++) {
            int idx = tid + i * 256;
            int r = idx >> 4, kk = idx & 15;
            As[kk][r] = (m0 + r < PP) ? A[(size_t)(m0 + r) * 512 + k0 + kk] : 0.f;
            Bs[kk][r] = (n0 + r < PP) ? Bk[(size_t)(n0 + r) * 512 + k0 + kk] : 0.f;
        }
        __syncthreads();
        #pragma unroll
        for (int kk = 0; kk < 16; kk++) {
            float a[4], b2[4];
            #pragma unroll
            for (int i = 0; i < 4; i++) a[i] = As[kk][ty * 4 + i];
            #pragma unroll
            for (int j = 0; j < 4; j++) b2[j] = Bs[kk][tx * 4 + j];
            #pragma unroll
            for (int i = 0; i < 4; i++)
                #pragma unroll
                for (int j = 0; j < 4; j++)
                    acc[i][j] += a[i] * b2[j];
        }
        __syncthreads();
    }
    #pragma unroll
    for (int i = 0; i < 4; i++) {
        int m = m0 + ty * 4 + i;
        if (m >= PP) continue;
        #pragma unroll
        for (int j = 0; j < 4; j++) {
            int n = n0 + tx * 4 + j;
            if (n < PP) C[(size_t)m * PP + n] = acc[i][j];
        }
    }
}

// =====================================================================
// 3) column argmax, two stages (validated in R4)
// =====================================================================
#define CHUNK 113   // 8 chunks: 7*113 + 109 = 900
__global__ void argmax_part_kernel()
{
    int bh = blockIdx.x;
    int ck = blockIdx.y;
    int r0 = ck * CHUNK;
    int len = min(CHUNK, PP - r0);
    const float* S0 = g_scores + (size_t)bh * PP * PP;
    for (int w = threadIdx.x; w < PP; w += 256) {
        const float* S = S0 + w;
        float best = -1e30f; int bi = 0;
        for (int r = 0; r < len; r++) {
            float v = S[(size_t)(r0 + r) * PP];
            if (v > best) { best = v; bi = r0 + r; }
        }
        g_pmax[(bh * 8 + ck) * PP + w] = best;
        g_pidx[(bh * 8 + ck) * PP + w] = bi;
    }
}

__global__ void argmax_reduce_kernel()
{
    int bh = blockIdx.x;
    int w = blockIdx.y * 256 + threadIdx.x;
    if (w >= PP) return;
    float best = -1e30f; int bi = 0;
    #pragma unroll
    for (int ck = 0; ck < 8; ck++) {
        float v = g_pmax[(bh * 8 + ck) * PP + w];
        if (v > best) { best = v; bi = g_pidx[(bh * 8 + ck) * PP + w]; }
    }
    g_idx[bh * PP + w] = bi;
}

// =====================================================================
// 4) gaussian modulation + /sqrt(dk) + row softmax, in place
// =====================================================================
__global__ void softmax_kernel()
{
    __shared__ float buf[PP];
    __shared__ float red[256];

    int row = blockIdx.x;
    int bh = row / PP, p0 = row % PP;
    int t = threadIdx.x;

    float ys0 = -1.f + (2.f / 29.f) * (float)(p0 / SIDE);
    float xs0 = -1.f + (2.f / 29.f) * (float)(p0 % SIDE);

    float* S = g_scores + (size_t)bh * PP * PP + (size_t)p0 * PP;
    const int* idx = g_idx + bh * PP;

    float lmax = -1e30f;
    for (int w = t; w < PP; w += 256) {
        int id = idx[w];
        float dy = ys0 - (float)(id / SIDE);
        float dx = xs0 - (float)(id % SIDE);
        float g = __expf(-(dx * dx + dy * dy) * (1.f / 50.f));
        float v = S[w] * g * 0.125f;
        buf[w] = v;
        lmax = fmaxf(lmax, v);
    }
    red[t] = lmax; __syncthreads();
    for (int s = 128; s > 0; s >>= 1) {
        if (t < s) red[t] = fmaxf(red[t], red[t + s]);
        __syncthreads();
    }
    float m = red[0];
    __syncthreads();

    float lsum = 0.f;
    for (int w = t; w < PP; w += 256) {
        float e = __expf(buf[w] - m);
        buf[w] = e;
        lsum += e;
    }
    red[t] = lsum; __syncthreads();
    for (int s = 128; s > 0; s >>= 1) {
        if (t < s) red[t] += red[t + s];
        __syncthreads();
    }
    float inv = 1.f / red[0];
    for (int w = t; w < PP; w += 256) S[w] = buf[w] * inv;
}

// =====================================================================
// common mma helpers (proven in R9)
// =====================================================================
#define LO_SCALE 2048.0f
#define LO_INV   (1.0f / 2048.0f)
#define X1_W     66

__device__ __forceinline__ void hmma_16x8x8(float& c0, float& c1, float& c2, float& c3,
                                            unsigned a0, unsigned a1, unsigned b0)
{
    asm volatile(
        "mma.sync.aligned.m16n8k8.row.col.f32.f16.f16.f32 "
        "{%0,%1,%2,%3}, {%4,%5}, {%6}, {%0,%1,%2,%3};\n"
        : "+f"(c0), "+f"(c1), "+f"(c2), "+f"(c3)
        : "r"(a0), "r"(a1), "r"(b0));
}

__device__ __forceinline__ unsigned pack_hh(__half a, __half b)
{
    __half2 h = __halves2half2(a, b);
    return *reinterpret_cast<unsigned*>(&h);
}

// hi = fp16(x); lo = fp16((x - hi) * 2048)
__device__ __forceinline__ void split2s(float a, float b, unsigned& hi, unsigned& lo)
{
    __half ha = __float2half_rn(a), hb = __float2half_rn(b);
    hi = pack_hh(ha, hb);
    lo = pack_hh(__float2half_rn((a - __half2float(ha)) * LO_SCALE),
                 __float2half_rn((b - __half2float(hb)) * LO_SCALE));
}

// =====================================================================
// 5a) conv1 via tensor cores — UNCHANGED from R9 (proven)
// =====================================================================
__global__ __launch_bounds__(256)
void conv1_mma_kernel(const float* __restrict__ w1, const float* __restrict__ b1)
{
    __shared__ char XpH[18 * X1_W * 16];
    __shared__ char XpL[18 * X1_W * 16];
    __shared__ unsigned W1H[9 * 4 * 32];
    __shared__ unsigned W1L[9 * 4 * 32];
    __shared__ float sb1[32];

    int n   = blockIdx.z;
    int ty0 = blockIdx.y * 16;
    int tx0 = blockIdx.x * 64;
    int tid = threadIdx.x;
    int wid = tid >> 5;
    int lane = tid & 31;
    int t = lane & 3;
    int g = lane >> 2;

    for (int i = tid; i < 9 * 4 * 32; i += 256) {
        int tap = i >> 7;
        int nt  = (i >> 5) & 3;
        int ln  = i & 31;
        int lt = ln & 3, lg = ln >> 2;
        int oc1 = nt * 8 + lg;
        split2s(w1[oc1 * 72 + (2 * lt) * 9 + tap],
                w1[oc1 * 72 + (2 * lt + 1) * 9 + tap], W1H[i], W1L[i]);
    }
    if (tid < 32) sb1[tid] = b1[tid];

    for (int e = tid; e < 18 * X1_W; e += 256) {
        int rI = e / X1_W, j = e % X1_W;
        int gy = ty0 - 1 + rI, gx = tx0 - 1 + j;
        bool inb = ((unsigned)gy < (unsigned)PP) && ((unsigned)gx < (unsigned)PP);
        unsigned rh[4], rl[4];
        #pragma unroll
        for (int icp = 0; icp < 4; icp++) {
            float f0 = 0.f, f1 = 0.f;
            if (inb) {
                const float* base = g_scores + (((size_t)(n * 8 + 2 * icp)) * PP + gy) * PP + gx;
                f0 = base[0];
                f1 = base[(size_t)PP * PP];
            }
            split2s(f0, f1, rh[icp], rl[icp]);
        }
        *(uint4*)(XpH + e * 16) = make_uint4(rh[0], rh[1], rh[2], rh[3]);
        *(uint4*)(XpL + e * 16) = make_uint4(rl[0], rl[1], rl[2], rl[3]);
    }
    __syncthreads();

    unsigned w1fh[9][4], w1fl[9][4];
    #pragma unroll
    for (int tap = 0; tap < 9; tap++)
        #pragma unroll
        for (int nt = 0; nt < 4; nt++) {
            w1fh[tap][nt] = W1H[(tap * 4 + nt) * 32 + lane];
            w1fl[tap][nt] = W1L[(tap * 4 + nt) * 32 + lane];
        }

    for (int it = wid; it < 64; it += 8) {
        int y = it >> 2, s = it & 3;
        float ah[4][4] = {};
        float al[4][4] = {};
        #pragma unroll
        for (int tap = 0; tap < 9; tap++) {
            int ky = tap / 3, kx = tap % 3;
            int j0 = s * 16 + kx + g;
            int boff = ((y + ky) * X1_W + j0) * 16 + t * 4;
            unsigned a0h = *(const unsigned*)(XpH + boff);
            unsigned a1h = *(const unsigned*)(XpH + boff + 8 * 16);
            unsigned a0l = *(const unsigned*)(XpL + boff);
            unsigned a1l = *(const unsigned*)(XpL + boff + 8 * 16);
            #pragma unroll
            for (int nt = 0; nt < 4; nt++) {
                hmma_16x8x8(ah[nt][0], ah[nt][1], ah[nt][2], ah[nt][3], a0h, a1h, w1fh[tap][nt]);
                hmma_16x8x8(al[nt][0], al[nt][1], al[nt][2], al[nt][3], a0l, a1l, w1fh[tap][nt]);
                hmma_16x8x8(al[nt][0], al[nt][1], al[nt][2], al[nt][3], a0h, a1h, w1fl[tap][nt]);
            }
        }
        int gy = ty0 + y;
        if (gy < PP) {
            int gx0 = tx0 + s * 16 + g;
            int gx8 = gx0 + 8;
            #pragma unroll
            for (int nt = 0; nt < 4; nt++) {
                int ocA = nt * 8 + 2 * t;
                float bA = sb1[ocA], bB = sb1[ocA + 1];
                float y0 = fmaxf(ah[nt][0] + al[nt][0] * LO_INV + bA, 0.f);
                float y1 = fmaxf(ah[nt][1] + al[nt][1] * LO_INV + bB, 0.f);
                float y2 = fmaxf(ah[nt][2] + al[nt][2] * LO_INV + bA, 0.f);
                float y3 = fmaxf(ah[nt][3] + al[nt][3] * LO_INV + bB, 0.f);
                size_t rowA = ((size_t)(n * C1 + ocA) * PP + gy) * PP;
                size_t rowB = ((size_t)(n * C1 + ocA + 1) * PP + gy) * PP;
                if (gx0 < PP) {
                    g_conv1[rowA + gx0] = y0;
                    g_conv1[rowB + gx0] = y1;
                }
                if (gx8 < PP) {
                    g_conv1[rowA + gx8] = y2;
                    g_conv1[rowB + gx8] = y3;
                }
            }
        }
    }
}

// =====================================================================
// 5b) conv2 via tensor cores — same proven pattern, per-kc 16B records,
//     NO swizzle. Reads fp32 g_conv1 (re-zero-padded), fuses value-dot.
//     Output tile: 64 cols x 8 rows. Grid (15, 113, 4).
// smem (dynamic ~94KB):
//   Xp2H/Xp2L: [4 kc][10 rows * 66 cols][8ch fp16 = 16B]
//   W2H/W2L:   [9 tap][4 kc][32 lane] u32
// =====================================================================
#define X2_NPIX   (10 * 66)
#define X2H_OFF   0
#define X2L_OFF   (4 * X2_NPIX * 16)                 // 42240
#define W2H_OFF2  (2 * 4 * X2_NPIX * 16)             // 84480
#define W2L_OFF2  (W2H_OFF2 + 4608)                  // 89088
#define SB2_OFF2  (W2L_OFF2 + 4608)                  // 93696
#define CONV2_SMEM (SB2_OFF2 + 32)                   // 93728

__global__ __launch_bounds__(256)
void conv2_mma_kernel(const float* __restrict__ w2, const float* __restrict__ b2,
                      const float* __restrict__ value)
{
    extern __shared__ char smem[];
    char* Xp2H = smem + X2H_OFF;
    char* Xp2L = smem + X2L_OFF;
    unsigned* W2H = (unsigned*)(smem + W2H_OFF2);
    unsigned* W2L = (unsigned*)(smem + W2L_OFF2);
    float* sb2 = (float*)(smem + SB2_OFF2);

    int n   = blockIdx.z;
    int ty0 = blockIdx.y * 8;
    int tx0 = blockIdx.x * 64;
    int tid = threadIdx.x;
    int wid = tid >> 5;
    int lane = tid & 31;
    int t = lane & 3;        // k-pair / oc-pair
    int g = lane >> 2;       // pixel row-in-fragment

    // ---- weight fragments: B[k = kc*8+2lt(+1)][n = oc] = w2[oc][ic][tap] ----
    for (int i = tid; i < 9 * 4 * 32; i += 256) {
        int tap = i >> 7;
        int kc  = (i >> 5) & 3;
        int ln  = i & 31;
        int lt = ln & 3, lg = ln >> 2;
        int ic0 = kc * 8 + 2 * lt;
        split2s(w2[lg * 288 + ic0 * 9 + tap],
                w2[lg * 288 + (ic0 + 1) * 9 + tap], W2H[i], W2L[i]);
    }
    if (tid < 8) sb2[tid] = b2[tid];

    // ---- input tile: rows gy=ty0-1+rI (rI 0..9), cols gx=tx0-1+j (j 0..65) ----
    // per kc: 8 channels kc*8 .. kc*8+7, zero-padded out of image
    for (int e = tid; e < X2_NPIX; e += 256) {
        int rI = e / X1_W, j = e % X1_W;
        int gy = ty0 - 1 + rI, gx = tx0 - 1 + j;
        bool inb = ((unsigned)gy < (unsigned)PP) && ((unsigned)gx < (unsigned)PP);
        #pragma unroll
        for (int kc = 0; kc < 4; kc++) {
            unsigned rh[4], rl[4];
            #pragma unroll
            for (int icp = 0; icp < 4; icp++) {
                float f0 = 0.f, f1 = 0.f;
                if (inb) {
                    const float* base = g_conv1 +
                        (((size_t)(n * C1 + kc * 8 + 2 * icp)) * PP + gy) * PP + gx;
                    f0 = base[0];
                    f1 = base[(size_t)PP * PP];
                }
                split2s(f0, f1, rh[icp], rl[icp]);
            }
            int off = (kc * X2_NPIX + e) * 16;
            *(uint4*)(Xp2H + off) = make_uint4(rh[0], rh[1], rh[2], rh[3]);
            *(uint4*)(Xp2L + off) = make_uint4(rl[0], rl[1], rl[2], rl[3]);
        }
    }
    __syncthreads();

    // ---- per-lane weight fragments ----
    unsigned w2fh[9][4], w2fl[9][4];
    #pragma unroll
    for (int tap = 0; tap < 9; tap++)
        #pragma unroll
        for (int kc = 0; kc < 4; kc++) {
            w2fh[tap][kc] = W2H[(tap * 4 + kc) * 32 + lane];
            w2fl[tap][kc] = W2L[(tap * 4 + kc) * 32 + lane];
        }

    // ---- warp = output row y (0..7); loop strips s 0..3; value-dot ----
    {
        int y = wid;
        float vb0 = sb2[2 * t];
        float vb1 = sb2[2 * t + 1];
        float rsum = 0.f;

        for (int s = 0; s < 4; s++) {
            float ah[4] = {};
            float al[4] = {};
            #pragma unroll
            for (int tap = 0; tap < 9; tap++) {
                int ky = tap / 3, kx = tap % 3;
                int j0 = s * 16 + kx + g;
                #pragma unroll
                for (int kc = 0; kc < 4; kc++) {
                    int boff = (kc * X2_NPIX + (y + ky) * X1_W + j0) * 16 + t * 4;
                    unsigned a0h = *(const unsigned*)(Xp2H + boff);
                    unsigned a1h = *(const unsigned*)(Xp2H + boff + 8 * 16);
                    unsigned a0l = *(const unsigned*)(Xp2L + boff);
                    unsigned a1l = *(const unsigned*)(Xp2L + boff + 8 * 16);
                    hmma_16x8x8(ah[0], ah[1], ah[2], ah[3], a0h, a1h, w2fh[tap][kc]);
                    hmma_16x8x8(al[0], al[1], al[2], al[3], a0l, a1l, w2fh[tap][kc]);
                    hmma_16x8x8(al[0], al[1], al[2], al[3], a0h, a1h, w2fl[tap][kc]);
                }
            }
            // lane (g,t): pixels x0 = s*16+g (c0,c1), x8 = x0+8 (c2,c3); oc 2t,2t+1
            int gx0 = tx0 + s * 16 + g;
            int gx8 = gx0 + 8;
            float z0 = fmaxf(ah[0] + al[0] * LO_INV + vb0, 0.f);
            float z1 = fmaxf(ah[1] + al[1] * LO_INV + vb1, 0.f);
            float z2 = fmaxf(ah[2] + al[2] * LO_INV + vb0, 0.f);
            float z3 = fmaxf(ah[3] + al[3] * LO_INV + vb1, 0.f);
            float v0 = (gx0 < PP) ? value[n * PP + gx0] : 0.f;
            float v8 = (gx8 < PP) ? value[n * PP + gx8] : 0.f;
            rsum += v0 * (z0 + z1) + v8 * (z2 + z3);
        }
        // full-warp sum: 16 pixels x 8 oc per strip, all strips accumulated
        #pragma unroll
        for (int off = 16; off > 0; off >>= 1)
            rsum += __shfl_xor_sync(0xffffffffu, rsum, off);
        int gy = ty0 + y;
        if (lane == 0 && gy < PP)
            g_part[(n * PP + gy) * 15 + blockIdx.x] = rsum;
    }
}

// =====================================================================
// 6) finalize: out[b][p] = (1/8) * sum_tiles partials
// =====================================================================
__global__ void finalize_kernel(float* __restrict__ out)
{
    int i = blockIdx.x * 256 + threadIdx.x;
    if (i >= BB * PP) return;
    float s = 0.f;
    #pragma unroll
    for (int t = 0; t < 15; t++) s += g_part[i * 15 + t];
    out[i] = s * 0.125f;
}

// =====================================================================
extern "C" void kernel_launch(void* const* d_in, const int* in_sizes, int n_in,
                              void* d_out, int out_size)
{
    const float* query = (const float*)d_in[0];
    const float* key_t = (const float*)d_in[1];
    const float* value = (const float*)d_in[2];
    const float* Wq    = (const float*)d_in[3];
    const float* bq    = (const float*)d_in[4];
    const float* Wk    = (const float*)d_in[5];
    const float* bk    = (const float*)d_in[6];
    const float* w1    = (const float*)d_in[7];
    const float* b1    = (const float*)d_in[8];
    const float* w2    = (const float*)d_in[9];
    const float* b2    = (const float*)d_in[10];

    static int smem_set = 0;
    if (!smem_set) {
        cudaFuncSetAttribute(conv2_mma_kernel,
                             cudaFuncAttributeMaxDynamicSharedMemorySize, CONV2_SMEM);
        smem_set = 1;
    }

    dim3 gp(57, 8);
    proj_kernel<<<gp, 256>>>(query, Wq, bq, 0);
    proj_kernel<<<gp, 256>>>(key_t, Wk, bk, 1);

    dim3 gs(15, 15, NBH);
    scores_kernel<<<gs, 256>>>();

    dim3 ga(NBH, 8);
    argmax_part_kernel<<<ga, 256>>>();
    dim3 gr(NBH, 4);
    argmax_reduce_kernel<<<gr, 256>>>();

    softmax_kernel<<<NBH * PP, 256>>>();

    dim3 g1(15, 57, BB);
    conv1_mma_kernel<<<g1, 256>>>(w1, b1);

    dim3 g2(15, 113, BB);
    conv2_mma_kernel<<<g2, 256, CONV2_SMEM>>>(w2, b2, value);

    finalize_kernel<<<15, 256>>>((float*)d_out);
}